// round 11
// baseline (speedup 1.0000x reference)
#include <cuda_runtime.h>
#include <cuda_fp16.h>
#include <cstdint>

#define N_NODES   100000
#define N_PAD     100096          // 782 * 128
#define NUM_RELS  16
#define NUM_BASES 8
#define D         128
#define KG        1024            // NUM_BASES*D (basis-agg block only)
#define KDIM      1152            // KG + D (full GEMM K)

// ---------------- scratch (device globals; zero-initialized at load) ----------
__device__ __half g_Ah[(size_t)N_PAD * KG];     // [Npad, 1024] fp16 GEMM A (basis block)
__device__ __half g_Wf[128 * KDIM];             // transposed: [n][k] fp16, zero-pad rows
__device__ __half g_hx[(size_t)N_PAD * D];      // fp16 copy of input x (padded)
__device__ __half g_h0[(size_t)N_PAD * D];      // fp16 hidden
__device__ __half g_h1[(size_t)N_PAD * D];
__device__ int   g_cnt[N_NODES];
__device__ int   g_off[N_NODES + 1];
__device__ int   g_cur[N_NODES];
__device__ int   g_csr[1600000];                // packed (type<<17)|src, grouped by dst

// ---------------- PTX helpers -------------------------------------------------
__device__ __forceinline__ uint32_t s2u(const void* p) {
    return (uint32_t)__cvta_generic_to_shared(p);
}
__device__ __forceinline__ void cp16(uint32_t smem, const void* gmem) {
    asm volatile("cp.async.cg.shared.global [%0], [%1], 16;\n" :: "r"(smem), "l"(gmem));
}
#define CP_COMMIT() asm volatile("cp.async.commit_group;\n" ::: "memory")
#define CP_WAIT(N)  asm volatile("cp.async.wait_group %0;\n" :: "n"(N) : "memory")

__device__ __forceinline__ void ffma2(uint64_t& d, uint64_t a, uint64_t b) {
    asm("fma.rn.f32x2 %0, %1, %2, %0;" : "+l"(d) : "l"(a), "l"(b));
}
__device__ __forceinline__ uint64_t pack_f2(float lo, float hi) {
    uint64_t r;
    asm("mov.b64 %0, {%1, %2};" : "=l"(r) : "f"(lo), "f"(hi));
    return r;
}
__device__ __forceinline__ float2 unpack_f2(uint64_t v) {
    float2 r;
    asm("mov.b64 {%0, %1}, %2;" : "=f"(r.x), "=f"(r.y) : "l"(v));
    return r;
}
__device__ __forceinline__ void ldsm4(uint32_t& r0, uint32_t& r1, uint32_t& r2, uint32_t& r3,
                                      uint32_t addr) {
    asm volatile("ldmatrix.sync.aligned.m8n8.x4.shared.b16 {%0,%1,%2,%3}, [%4];"
                 : "=r"(r0), "=r"(r1), "=r"(r2), "=r"(r3) : "r"(addr));
}
__device__ __forceinline__ void mma_f16(float4& c,
                                        uint32_t a0, uint32_t a1, uint32_t a2, uint32_t a3,
                                        uint32_t b0, uint32_t b1) {
    asm volatile(
        "mma.sync.aligned.m16n8k16.row.col.f32.f16.f16.f32 "
        "{%0,%1,%2,%3}, {%4,%5,%6,%7}, {%8,%9}, {%0,%1,%2,%3};\n"
        : "+f"(c.x), "+f"(c.y), "+f"(c.z), "+f"(c.w)
        : "r"(a0), "r"(a1), "r"(a2), "r"(a3), "r"(b0), "r"(b1));
}

// ---------------- CSR build (g_cnt is zero on entry; k_scan re-zeroes it) -----
__global__ void k_count_x(const int* __restrict__ dst, int E, const float* __restrict__ x) {
    int i = blockIdx.x * blockDim.x + threadIdx.x;
    if (i < E) atomicAdd(&g_cnt[dst[i]], 1);
    if (i < N_NODES * (D / 2)) {
        float2 v = reinterpret_cast<const float2*>(x)[i];
        reinterpret_cast<__half2*>(g_hx)[i] = __floats2half2_rn(v.x, v.y);
    }
}
__global__ void k_scan() {
    __shared__ int ssum[1024];
    const int chunk = (N_NODES + 1023) / 1024;
    int t = threadIdx.x;
    int b = t * chunk;
    int e = b + chunk; if (e > N_NODES) e = N_NODES;
    int s = 0;
    for (int i = b; i < e; ++i) s += g_cnt[i];
    ssum[t] = s;
    __syncthreads();
    for (int off = 1; off < 1024; off <<= 1) {
        int v = (t >= off) ? ssum[t - off] : 0;
        __syncthreads();
        ssum[t] += v;
        __syncthreads();
    }
    int run = (t == 0) ? 0 : ssum[t - 1];
    for (int i = b; i < e; ++i) {
        g_off[i] = run; g_cur[i] = run;
        run += g_cnt[i];
        g_cnt[i] = 0;                    // re-zero for the next kernel_launch call
    }
    if (t == 0) g_off[N_NODES] = ssum[1023];
}
__global__ void k_scatter(const int* __restrict__ src, const int* __restrict__ dst,
                          const int* __restrict__ typ, int E) {
    int e = blockIdx.x * blockDim.x + threadIdx.x;
    if (e < E) {
        int p = atomicAdd(&g_cur[dst[e]], 1);
        g_csr[p] = (typ[e] << 17) | src[e];
    }
}

// ---------------- weight: transpose to [n][k], fp16 ---------------------------
__global__ void k_make_w(const float* __restrict__ bases, const float* __restrict__ root, int dout) {
    int idx = blockIdx.x * blockDim.x + threadIdx.x;
    if (idx >= 128 * KDIM) return;
    int n = idx / KDIM, k = idx % KDIM;
    float v = 0.f;
    if (n < dout)
        v = (k < KG) ? bases[k * dout + n]
                     : root[(k - KG) * dout + n];
    g_Wf[idx] = __float2half_rn(v);
}

// ---------------- pull-aggregate: 2 warps per dst node (feature split) --------
// warp task = (node, half); each warp owns 64 features, 2 per lane.
// acc shrinks to 8 u64 regs -> natural regcount ~50 -> ~5 blocks/SM resident.
#define PULL_WARPS 8
__global__ void k_pull(const __half* __restrict__ hin, const float* __restrict__ comp) {
    __shared__ int s_cnt[PULL_WARPS][16];
    __shared__ __align__(16) float2 s_sc[PULL_WARPS][16][8];  // (c,c) duplicated
    const int w = threadIdx.x >> 5, lane = threadIdx.x & 31;
    const int wg = blockIdx.x * PULL_WARPS + w;
    const int nwarps = gridDim.x * PULL_WARPS;

    for (int task = wg; task < 2 * N_NODES; task += nwarps) {
        const int n = task >> 1, half = task & 1;
        const int off = g_off[n], end = g_off[n + 1];

        if (lane < 16) s_cnt[w][lane] = 0;
        __syncwarp();
        for (int e = off + lane; e < end; e += 32)
            atomicAdd(&s_cnt[w][g_csr[e] >> 17], 1);
        __syncwarp();
        #pragma unroll
        for (int idx = lane; idx < 128; idx += 32) {
            int r = idx >> 3, b = idx & 7;
            int c = s_cnt[w][r];
            float inv = (c > 0) ? (1.0f / (float)c) : 0.0f;
            float cc = comp[idx] * inv;
            s_sc[w][r][b] = make_float2(cc, cc);
        }
        __syncwarp();

        uint64_t acc[NUM_BASES];
        #pragma unroll
        for (int b = 0; b < NUM_BASES; ++b) acc[b] = 0ull;

        const __half* hbase = hin + half * 64 + lane * 2;
        for (int e = off; e < end; ++e) {
            const int p   = g_csr[e];
            const int src = p & 131071;
            const int r   = p >> 17;
            const uint32_t hv = *reinterpret_cast<const uint32_t*>(hbase + (size_t)src * D);
            float2 f = __half22float2(*reinterpret_cast<const __half2*>(&hv));
            const uint64_t x0 = pack_f2(f.x, f.y);
            const ulonglong2* cp = reinterpret_cast<const ulonglong2*>(&s_sc[w][r][0]);
            #pragma unroll
            for (int q = 0; q < 4; ++q) {
                const ulonglong2 c2 = cp[q];   // broadcast LDS.128
                ffma2(acc[2 * q],     x0, c2.x);
                ffma2(acc[2 * q + 1], x0, c2.y);
            }
        }

        __half* Ar = g_Ah + (size_t)n * KG + half * 64 + lane * 2;
        #pragma unroll
        for (int b = 0; b < NUM_BASES; ++b) {
            float2 v = unpack_f2(acc[b]);
            __half2 o = __floats2half2_rn(v.x, v.y);
            *reinterpret_cast<__half2*>(Ar + b * D) = o;
        }
    }
}

// ---------------- fp16 tensor-core GEMM (ldmatrix + 3-stage cp.async) ---------
// A = [g_Ah (k<1024) | hin (k>=1024)]; B = g_Wf[128][1152]
template <int BN, int HALF_OUT>
__global__ __launch_bounds__(256, 2) void k_gemm(const __half* __restrict__ hin,
                                                 const float* __restrict__ bias,
                                                 void* __restrict__ outp,
                                                 int Nout, int relu, int predM) {
    constexpr int BK   = 32;
    constexpr int ROWB = (BK + 8) * 2;              // 80 bytes per smem row
    constexpr int JT   = BN / 32;                   // n8 tiles per warp
    constexpr int STAGE = (128 + BN) * ROWB;        // bytes per pipeline stage
    constexpr int NK   = KDIM / BK;                 // 36 (32 from g_Ah, 4 from hin)
    extern __shared__ char sm[];

    const int tid = threadIdx.x, wid = tid >> 5, lane = tid & 31;
    const int wm = wid >> 2, wn = wid & 3;
    const int g = lane >> 2, t = lane & 3;
    const int m0 = blockIdx.x * 128;
    const uint32_t smb = s2u(sm);

    const uint32_t a_base = (uint32_t)((wm * 64 + (lane & 15)) * ROWB + (lane >> 4) * 16);
    const uint32_t b_base = (uint32_t)((wn * (JT * 8) + ((lane >> 4) & 1) * 8 + (lane & 7)) * ROWB
                                       + ((lane >> 3) & 1) * 16);

    float4 c[4][JT];
    #pragma unroll
    for (int i = 0; i < 4; ++i)
        #pragma unroll
        for (int j = 0; j < JT; ++j) c[i][j] = make_float4(0.f, 0.f, 0.f, 0.f);

    auto load_stage = [&](int st, int kt) {
        const uint32_t base = smb + st * STAGE;
        #pragma unroll
        for (int i = 0; i < 2; ++i) {
            const int task = tid + i * 256;
            const int row = task >> 2, ch = task & 3;
            const __half* src = (kt < KG)
                ? g_Ah + (size_t)(m0 + row) * KG + kt + ch * 8
                : hin  + (size_t)(m0 + row) * D + (kt - KG) + ch * 8;
            cp16(base + row * ROWB + ch * 16, src);
        }
        #pragma unroll
        for (int i = 0; i < (BN * 4) / 256; ++i) {
            const int task = tid + i * 256;
            const int row = task >> 2, ch = task & 3;
            cp16(base + 128 * ROWB + row * ROWB + ch * 16,
                 g_Wf + (size_t)row * KDIM + kt + ch * 8);
        }
        CP_COMMIT();
    };

    load_stage(0, 0);
    load_stage(1, BK);

    for (int it = 0; it < NK; ++it) {
        if (it < NK - 1) { CP_WAIT(1); } else { CP_WAIT(0); }
        __syncthreads();
        if (it + 2 < NK) load_stage((it + 2) % 3, (it + 2) * BK);

        const uint32_t sA = smb + (it % 3) * STAGE;
        const uint32_t sB = sA + 128 * ROWB;
        #pragma unroll
        for (int kk = 0; kk < BK; kk += 16) {
            uint32_t a[4][4];
            #pragma unroll
            for (int i = 0; i < 4; ++i)
                ldsm4(a[i][0], a[i][1], a[i][2], a[i][3],
                      sA + a_base + i * (16 * ROWB) + kk * 2);
            uint32_t b[JT][2];
            #pragma unroll
            for (int jc = 0; jc < JT / 2; ++jc)
                ldsm4(b[2 * jc][0], b[2 * jc][1], b[2 * jc + 1][0], b[2 * jc + 1][1],
                      sB + b_base + jc * (16 * ROWB) + kk * 2);
            #pragma unroll
            for (int i = 0; i < 4; ++i)
                #pragma unroll
                for (int j = 0; j < JT; ++j)
                    mma_f16(c[i][j], a[i][0], a[i][1], a[i][2], a[i][3], b[j][0], b[j][1]);
        }
    }

    // epilogue
    #pragma unroll
    for (int i = 0; i < 4; ++i) {
        const int r0 = m0 + wm * 64 + i * 16 + g;
        #pragma unroll
        for (int j = 0; j < JT; ++j) {
            const int col = wn * (JT * 8) + j * 8 + 2 * t;
            if (col < Nout) {
                float b0 = bias[col];
                float b1 = (col + 1 < Nout) ? bias[col + 1] : 0.f;
                float v00 = c[i][j].x + b0, v01 = c[i][j].y + b1;
                float v10 = c[i][j].z + b0, v11 = c[i][j].w + b1;
                if (relu) {
                    v00 = fmaxf(v00, 0.f); v01 = fmaxf(v01, 0.f);
                    v10 = fmaxf(v10, 0.f); v11 = fmaxf(v11, 0.f);
                }
                if (HALF_OUT) {
                    __half* o = (__half*)outp;
                    __half2 h0 = __floats2half2_rn(v00, v01);
                    __half2 h1 = __floats2half2_rn(v10, v11);
                    *reinterpret_cast<__half2*>(o + (size_t)r0 * Nout + col) = h0;
                    *reinterpret_cast<__half2*>(o + (size_t)(r0 + 8) * Nout + col) = h1;
                } else {
                    float* o = (float*)outp;
                    const bool c1ok = (col + 1 < Nout);
                    if (!predM || r0 < N_NODES) {
                        o[(size_t)r0 * Nout + col] = v00;
                        if (c1ok) o[(size_t)r0 * Nout + col + 1] = v01;
                    }
                    if (!predM || r0 + 8 < N_NODES) {
                        o[(size_t)(r0 + 8) * Nout + col] = v10;
                        if (c1ok) o[(size_t)(r0 + 8) * Nout + col + 1] = v11;
                    }
                }
            }
        }
    }
}

// ---------------- launch ------------------------------------------------------
extern "C" void kernel_launch(void* const* d_in, const int* in_sizes, int n_in,
                              void* d_out, int out_size) {
    const float* x      = (const float*)d_in[0];
    const int*   esrc   = (const int*)  d_in[1];
    const int*   edst   = (const int*)  d_in[2];
    const int*   etyp   = (const int*)  d_in[3];
    const float* bases0 = (const float*)d_in[4];
    const float* comp0  = (const float*)d_in[5];
    const float* root0  = (const float*)d_in[6];
    const float* bias0  = (const float*)d_in[7];
    const float* bases1 = (const float*)d_in[8];
    const float* comp1  = (const float*)d_in[9];
    const float* root1  = (const float*)d_in[10];
    const float* bias1  = (const float*)d_in[11];
    const float* bases2 = (const float*)d_in[12];
    const float* comp2  = (const float*)d_in[13];
    const float* root2  = (const float*)d_in[14];
    const float* bias2  = (const float*)d_in[15];
    float* out = (float*)d_out;
    const int E = in_sizes[1];

    void* p;
    cudaGetSymbolAddress(&p, g_hx); __half* hx = (__half*)p;
    cudaGetSymbolAddress(&p, g_h0); __half* h0 = (__half*)p;
    cudaGetSymbolAddress(&p, g_h1); __half* h1 = (__half*)p;

    const int smem128 = 3 * (128 + 128) * 80;   // 61440
    const int smem64  = 3 * (128 + 64) * 80;    // 46080
    cudaFuncSetAttribute(k_gemm<128, 1>, cudaFuncAttributeMaxDynamicSharedMemorySize, smem128);
    cudaFuncSetAttribute(k_gemm<64, 0>,  cudaFuncAttributeMaxDynamicSharedMemorySize, smem64);

    // CSR (g_cnt zeroed by previous call's k_scan; device globals start zero)
    k_count_x<<<(N_NODES * (D / 2) + 255) / 256, 256>>>(edst, E, x);
    k_scan   <<<1, 1024>>>();
    k_scatter<<<(E + 255) / 256, 256>>>(esrc, edst, etyp, E);

    const int wgrid = (128 * KDIM + 255) / 256;   // 576
    const int ggrid = N_PAD / 128;                // 782

    // layer 0  (pull launched 4th overall -> lands in ncu's capture window)
    k_pull  <<<2048, 256>>>(hx, comp0);
    k_make_w<<<wgrid, 256>>>(bases0, root0, D);
    k_gemm<128, 1><<<ggrid, 256, smem128>>>(hx, bias0, h0, D, 1, 0);

    // layer 1
    k_pull  <<<2048, 256>>>(h0, comp1);
    k_make_w<<<wgrid, 256>>>(bases1, root1, D);
    k_gemm<128, 1><<<ggrid, 256, smem128>>>(h0, bias1, h1, D, 1, 0);

    // layer 2 (d_out = 40)
    k_pull  <<<2048, 256>>>(h1, comp2);
    k_make_w<<<wgrid, 256>>>(bases2, root2, 40);
    k_gemm<64, 0><<<ggrid, 256, smem64>>>(h1, bias2, out, 40, 0, 1);
}

// round 12
// speedup vs baseline: 1.1871x; 1.1871x over previous
#include <cuda_runtime.h>
#include <cuda_fp16.h>
#include <cstdint>

#define N_NODES   100000
#define N_PAD     100096          // 782 * 128
#define NUM_RELS  16
#define NUM_BASES 8
#define D         128
#define KG        1024            // NUM_BASES*D
#define KDIM      1152            // KG + D (full GEMM K)

// ---------------- scratch (device globals; zero-initialized at load) ----------
__device__ __half g_Ah[(size_t)N_PAD * KDIM];   // [Npad, 1152] fp16 GEMM A (incl self)
__device__ __half g_W3[3][128 * KDIM];          // per-layer weights, [n][k], zero-pad
__device__ __half g_hx[(size_t)N_PAD * D];      // fp16 copy of input x
__device__ __half g_h0[(size_t)N_PAD * D];      // fp16 hidden
__device__ __half g_h1[(size_t)N_PAD * D];
__device__ int   g_cnt[N_NODES];
__device__ int   g_off[N_NODES + 1];
__device__ int   g_cur[N_NODES];
__device__ int   g_csr[1600000];                // packed (type<<17)|src, grouped by dst

// ---------------- PTX helpers -------------------------------------------------
__device__ __forceinline__ uint32_t s2u(const void* p) {
    return (uint32_t)__cvta_generic_to_shared(p);
}
__device__ __forceinline__ void cp16(uint32_t smem, const void* gmem) {
    asm volatile("cp.async.cg.shared.global [%0], [%1], 16;\n" :: "r"(smem), "l"(gmem));
}
#define CP_COMMIT() asm volatile("cp.async.commit_group;\n" ::: "memory")
#define CP_WAIT(N)  asm volatile("cp.async.wait_group %0;\n" :: "n"(N) : "memory")

__device__ __forceinline__ void ffma2(uint64_t& d, uint64_t a, uint64_t b) {
    asm("fma.rn.f32x2 %0, %1, %2, %0;" : "+l"(d) : "l"(a), "l"(b));
}
__device__ __forceinline__ uint64_t pack_f2(float lo, float hi) {
    uint64_t r;
    asm("mov.b64 %0, {%1, %2};" : "=l"(r) : "f"(lo), "f"(hi));
    return r;
}
__device__ __forceinline__ float2 unpack_f2(uint64_t v) {
    float2 r;
    asm("mov.b64 {%0, %1}, %2;" : "=f"(r.x), "=f"(r.y) : "l"(v));
    return r;
}
__device__ __forceinline__ void ldsm4(uint32_t& r0, uint32_t& r1, uint32_t& r2, uint32_t& r3,
                                      uint32_t addr) {
    asm volatile("ldmatrix.sync.aligned.m8n8.x4.shared.b16 {%0,%1,%2,%3}, [%4];"
                 : "=r"(r0), "=r"(r1), "=r"(r2), "=r"(r3) : "r"(addr));
}
__device__ __forceinline__ void mma_f16(float4& c,
                                        uint32_t a0, uint32_t a1, uint32_t a2, uint32_t a3,
                                        uint32_t b0, uint32_t b1) {
    asm volatile(
        "mma.sync.aligned.m16n8k16.row.col.f32.f16.f16.f32 "
        "{%0,%1,%2,%3}, {%4,%5,%6,%7}, {%8,%9}, {%0,%1,%2,%3};\n"
        : "+f"(c.x), "+f"(c.y), "+f"(c.z), "+f"(c.w)
        : "r"(a0), "r"(a1), "r"(a2), "r"(a3), "r"(b0), "r"(b1));
}

// ---------------- fused: zero counters + x -> fp16 -----------------------------
__global__ void k_init(const float* __restrict__ x) {
    int i = blockIdx.x * blockDim.x + threadIdx.x;
    if (i < N_NODES) g_cnt[i] = 0;
    if (i < N_NODES * (D / 2)) {
        float2 v = reinterpret_cast<const float2*>(x)[i];
        reinterpret_cast<__half2*>(g_hx)[i] = __floats2half2_rn(v.x, v.y);
    }
}

// ---------------- CSR build --------------------------------------------------
__global__ void k_count(const int* __restrict__ dst, int E) {
    int e = blockIdx.x * blockDim.x + threadIdx.x;
    if (e < E) atomicAdd(&g_cnt[dst[e]], 1);
}
__global__ void k_scan() {
    __shared__ int ssum[1024];
    const int chunk = (N_NODES + 1023) / 1024;
    int t = threadIdx.x;
    int b = t * chunk;
    int e = b + chunk; if (e > N_NODES) e = N_NODES;
    int s = 0;
    for (int i = b; i < e; ++i) s += g_cnt[i];
    ssum[t] = s;
    __syncthreads();
    for (int off = 1; off < 1024; off <<= 1) {
        int v = (t >= off) ? ssum[t - off] : 0;
        __syncthreads();
        ssum[t] += v;
        __syncthreads();
    }
    int run = (t == 0) ? 0 : ssum[t - 1];
    for (int i = b; i < e; ++i) {
        g_off[i] = run; g_cur[i] = run;
        run += g_cnt[i];
    }
    if (t == 0) g_off[N_NODES] = ssum[1023];
}
__global__ void k_scatter(const int* __restrict__ src, const int* __restrict__ dst,
                          const int* __restrict__ typ, int E) {
    int e = blockIdx.x * blockDim.x + threadIdx.x;
    if (e < E) {
        int p = atomicAdd(&g_cur[dst[e]], 1);
        g_csr[p] = (typ[e] << 17) | src[e];
    }
}

// ---------------- weights: all 3 layers in one launch --------------------------
__global__ void k_make_w_all(const float* __restrict__ bases0, const float* __restrict__ root0,
                             const float* __restrict__ bases1, const float* __restrict__ root1,
                             const float* __restrict__ bases2, const float* __restrict__ root2) {
    int idx = blockIdx.x * blockDim.x + threadIdx.x;
    if (idx >= 3 * 128 * KDIM) return;
    const int layer = idx / (128 * KDIM);
    const int rem = idx % (128 * KDIM);
    const int n = rem / KDIM, k = rem % KDIM;
    const float* bases = (layer == 0) ? bases0 : (layer == 1) ? bases1 : bases2;
    const float* root  = (layer == 0) ? root0  : (layer == 1) ? root1  : root2;
    const int dout     = (layer == 2) ? 40 : 128;
    float v = 0.f;
    if (n < dout)
        v = (k < KG) ? bases[k * dout + n]
                     : root[(k - KG) * dout + n];
    g_W3[layer][rem] = __float2half_rn(v);
}

// ---------------- pull-aggregate: warp per dst node (R5 body, persistent) -----
#define PULL_WARPS 8
__global__ void k_pull(const __half* __restrict__ hin, const float* __restrict__ comp) {
    __shared__ int s_cnt[PULL_WARPS][16];
    __shared__ __align__(16) float2 s_sc[PULL_WARPS][16][8];  // (c,c) duplicated
    const int w = threadIdx.x >> 5, lane = threadIdx.x & 31;
    const int wg = blockIdx.x * PULL_WARPS + w;
    const int nwarps = gridDim.x * PULL_WARPS;

    for (int n = wg; n < N_NODES; n += nwarps) {
        const int off = g_off[n], end = g_off[n + 1];
        if (lane < 16) s_cnt[w][lane] = 0;
        __syncwarp();
        for (int e = off + lane; e < end; e += 32)
            atomicAdd(&s_cnt[w][g_csr[e] >> 17], 1);
        __syncwarp();
        #pragma unroll
        for (int idx = lane; idx < 128; idx += 32) {
            int r = idx >> 3, b = idx & 7;
            int c = s_cnt[w][r];
            float inv = (c > 0) ? (1.0f / (float)c) : 0.0f;
            float cc = comp[idx] * inv;
            s_sc[w][r][b] = make_float2(cc, cc);
        }
        __syncwarp();

        uint64_t acc[NUM_BASES][2];
        #pragma unroll
        for (int b = 0; b < NUM_BASES; ++b) { acc[b][0] = 0ull; acc[b][1] = 0ull; }

        for (int e = off; e < end; ++e) {
            const int p   = g_csr[e];
            const int src = p & 131071;
            const int r   = p >> 17;
            const uint2 hv = *reinterpret_cast<const uint2*>(hin + (size_t)src * D + lane * 4);
            float2 f0 = __half22float2(*reinterpret_cast<const __half2*>(&hv.x));
            float2 f1 = __half22float2(*reinterpret_cast<const __half2*>(&hv.y));
            const uint64_t x0 = pack_f2(f0.x, f0.y);
            const uint64_t x1 = pack_f2(f1.x, f1.y);
            const ulonglong2* cp = reinterpret_cast<const ulonglong2*>(&s_sc[w][r][0]);
            #pragma unroll
            for (int q = 0; q < 4; ++q) {
                const ulonglong2 c2 = cp[q];   // broadcast LDS.128
                ffma2(acc[2 * q][0],     x0, c2.x);
                ffma2(acc[2 * q][1],     x1, c2.x);
                ffma2(acc[2 * q + 1][0], x0, c2.y);
                ffma2(acc[2 * q + 1][1], x1, c2.y);
            }
        }
        __half* Ar = g_Ah + (size_t)n * KDIM + lane * 4;
        #pragma unroll
        for (int b = 0; b < NUM_BASES; ++b) {
            float2 lo = unpack_f2(acc[b][0]);
            float2 hi = unpack_f2(acc[b][1]);
            __half2 o0 = __floats2half2_rn(lo.x, lo.y);
            __half2 o1 = __floats2half2_rn(hi.x, hi.y);
            uint2 u;
            u.x = *reinterpret_cast<uint32_t*>(&o0);
            u.y = *reinterpret_cast<uint32_t*>(&o1);
            *reinterpret_cast<uint2*>(Ar + b * D) = u;
        }
        const uint2 sv = *reinterpret_cast<const uint2*>(hin + (size_t)n * D + lane * 4);
        *reinterpret_cast<uint2*>(Ar + NUM_BASES * D) = sv;
    }
}

// ---------------- fp16 tensor-core GEMM (ldmatrix + 3-stage cp.async) ---------
template <int BN, int HALF_OUT>
__global__ __launch_bounds__(256, 2) void k_gemm(const __half* __restrict__ W,
                                                 const float* __restrict__ bias,
                                                 void* __restrict__ outp,
                                                 int Nout, int relu, int predM) {
    constexpr int BK   = 32;
    constexpr int ROWB = (BK + 8) * 2;              // 80 bytes per smem row
    constexpr int JT   = BN / 32;                   // n8 tiles per warp
    constexpr int STAGE = (128 + BN) * ROWB;        // bytes per pipeline stage
    constexpr int NK   = KDIM / BK;                 // 36
    extern __shared__ char sm[];

    const int tid = threadIdx.x, wid = tid >> 5, lane = tid & 31;
    const int wm = wid >> 2, wn = wid & 3;
    const int g = lane >> 2, t = lane & 3;
    const int m0 = blockIdx.x * 128;
    const uint32_t smb = s2u(sm);

    const uint32_t a_base = (uint32_t)((wm * 64 + (lane & 15)) * ROWB + (lane >> 4) * 16);
    const uint32_t b_base = (uint32_t)((wn * (JT * 8) + ((lane >> 4) & 1) * 8 + (lane & 7)) * ROWB
                                       + ((lane >> 3) & 1) * 16);

    float4 c[4][JT];
    #pragma unroll
    for (int i = 0; i < 4; ++i)
        #pragma unroll
        for (int j = 0; j < JT; ++j) c[i][j] = make_float4(0.f, 0.f, 0.f, 0.f);

    auto load_stage = [&](int st, int kt) {
        const uint32_t base = smb + st * STAGE;
        #pragma unroll
        for (int i = 0; i < 2; ++i) {
            const int task = tid + i * 256;
            const int row = task >> 2, ch = task & 3;
            cp16(base + row * ROWB + ch * 16,
                 g_Ah + (size_t)(m0 + row) * KDIM + kt + ch * 8);
        }
        #pragma unroll
        for (int i = 0; i < (BN * 4) / 256; ++i) {
            const int task = tid + i * 256;
            const int row = task >> 2, ch = task & 3;
            cp16(base + 128 * ROWB + row * ROWB + ch * 16,
                 W + (size_t)row * KDIM + kt + ch * 8);
        }
        CP_COMMIT();
    };

    load_stage(0, 0);
    load_stage(1, BK);

    for (int it = 0; it < NK; ++it) {
        if (it < NK - 1) { CP_WAIT(1); } else { CP_WAIT(0); }
        __syncthreads();
        if (it + 2 < NK) load_stage((it + 2) % 3, (it + 2) * BK);

        const uint32_t sA = smb + (it % 3) * STAGE;
        const uint32_t sB = sA + 128 * ROWB;
        #pragma unroll
        for (int kk = 0; kk < BK; kk += 16) {
            uint32_t a[4][4];
            #pragma unroll
            for (int i = 0; i < 4; ++i)
                ldsm4(a[i][0], a[i][1], a[i][2], a[i][3],
                      sA + a_base + i * (16 * ROWB) + kk * 2);
            uint32_t b[JT][2];
            #pragma unroll
            for (int jc = 0; jc < JT / 2; ++jc)
                ldsm4(b[2 * jc][0], b[2 * jc][1], b[2 * jc + 1][0], b[2 * jc + 1][1],
                      sB + b_base + jc * (16 * ROWB) + kk * 2);
            #pragma unroll
            for (int i = 0; i < 4; ++i)
                #pragma unroll
                for (int j = 0; j < JT; ++j)
                    mma_f16(c[i][j], a[i][0], a[i][1], a[i][2], a[i][3], b[j][0], b[j][1]);
        }
    }

    // epilogue
    #pragma unroll
    for (int i = 0; i < 4; ++i) {
        const int r0 = m0 + wm * 64 + i * 16 + g;
        #pragma unroll
        for (int j = 0; j < JT; ++j) {
            const int col = wn * (JT * 8) + j * 8 + 2 * t;
            if (col < Nout) {
                float b0 = bias[col];
                float b1 = (col + 1 < Nout) ? bias[col + 1] : 0.f;
                float v00 = c[i][j].x + b0, v01 = c[i][j].y + b1;
                float v10 = c[i][j].z + b0, v11 = c[i][j].w + b1;
                if (relu) {
                    v00 = fmaxf(v00, 0.f); v01 = fmaxf(v01, 0.f);
                    v10 = fmaxf(v10, 0.f); v11 = fmaxf(v11, 0.f);
                }
                if (HALF_OUT) {
                    __half* o = (__half*)outp;
                    __half2 h0 = __floats2half2_rn(v00, v01);
                    __half2 h1 = __floats2half2_rn(v10, v11);
                    *reinterpret_cast<__half2*>(o + (size_t)r0 * Nout + col) = h0;
                    *reinterpret_cast<__half2*>(o + (size_t)(r0 + 8) * Nout + col) = h1;
                } else {
                    float* o = (float*)outp;
                    const bool c1ok = (col + 1 < Nout);
                    if (!predM || r0 < N_NODES) {
                        o[(size_t)r0 * Nout + col] = v00;
                        if (c1ok) o[(size_t)r0 * Nout + col + 1] = v01;
                    }
                    if (!predM || r0 + 8 < N_NODES) {
                        o[(size_t)(r0 + 8) * Nout + col] = v10;
                        if (c1ok) o[(size_t)(r0 + 8) * Nout + col + 1] = v11;
                    }
                }
            }
        }
    }
}

// ---------------- launch ------------------------------------------------------
extern "C" void kernel_launch(void* const* d_in, const int* in_sizes, int n_in,
                              void* d_out, int out_size) {
    const float* x      = (const float*)d_in[0];
    const int*   esrc   = (const int*)  d_in[1];
    const int*   edst   = (const int*)  d_in[2];
    const int*   etyp   = (const int*)  d_in[3];
    const float* bases0 = (const float*)d_in[4];
    const float* comp0  = (const float*)d_in[5];
    const float* root0  = (const float*)d_in[6];
    const float* bias0  = (const float*)d_in[7];
    const float* bases1 = (const float*)d_in[8];
    const float* comp1  = (const float*)d_in[9];
    const float* root1  = (const float*)d_in[10];
    const float* bias1  = (const float*)d_in[11];
    const float* bases2 = (const float*)d_in[12];
    const float* comp2  = (const float*)d_in[13];
    const float* root2  = (const float*)d_in[14];
    const float* bias2  = (const float*)d_in[15];
    float* out = (float*)d_out;
    const int E = in_sizes[1];

    void* p;
    cudaGetSymbolAddress(&p, g_hx); __half* hx = (__half*)p;
    cudaGetSymbolAddress(&p, g_h0); __half* h0 = (__half*)p;
    cudaGetSymbolAddress(&p, g_h1); __half* h1 = (__half*)p;
    cudaGetSymbolAddress(&p, g_W3); __half* w3 = (__half*)p;
    __half* w0 = w3;
    __half* w1 = w3 + (size_t)128 * KDIM;
    __half* w2 = w3 + (size_t)2 * 128 * KDIM;

    const int smem128 = 3 * (128 + 128) * 80;   // 61440
    const int smem64  = 3 * (128 + 64) * 80;    // 46080
    cudaFuncSetAttribute(k_gemm<128, 1>, cudaFuncAttributeMaxDynamicSharedMemorySize, smem128);
    cudaFuncSetAttribute(k_gemm<64, 0>,  cudaFuncAttributeMaxDynamicSharedMemorySize, smem64);

    // init + CSR (reused by all 3 layers)
    k_init   <<<(N_NODES * (D / 2) + 255) / 256, 256>>>(x);
    k_count  <<<(E + 255) / 256, 256>>>(edst, E);
    k_scan   <<<1, 1024>>>();
    k_scatter<<<(E + 255) / 256, 256>>>(esrc, edst, etyp, E);

    // all layer weights in one launch
    k_make_w_all<<<(3 * 128 * KDIM + 255) / 256, 256>>>(bases0, root0, bases1, root1,
                                                        bases2, root2);

    const int pgrid = 456;            // 3 CTAs/SM * 152 SMs — persistent, 1 wave
    const int ggrid = N_PAD / 128;    // 782

    // layer 0
    k_pull<<<pgrid, 256>>>(hx, comp0);
    k_gemm<128, 1><<<ggrid, 256, smem128>>>(w0, bias0, h0, D, 1, 0);

    // layer 1
    k_pull<<<pgrid, 256>>>(h0, comp1);
    k_gemm<128, 1><<<ggrid, 256, smem128>>>(w1, bias1, h1, D, 1, 0);

    // layer 2 (d_out = 40)
    k_pull<<<pgrid, 256>>>(h1, comp2);
    k_gemm<64, 0><<<ggrid, 256, smem64>>>(w2, bias2, out, 40, 0, 1);
}